// round 1
// baseline (speedup 1.0000x reference)
#include <cuda_runtime.h>
#include <cuda_bf16.h>
#include <cstdint>

#define VOCAB 50257
#define BATCH 512
#define SEQ   512

// Interleaved weight table: Wt[v] = (W[0][v], W[1][v]).
// Device-global scratch (no allocation allowed).
__device__ float2 g_Wt[VOCAB];

// Pack W [2, V] row-major into float2 [V].
__global__ void pack_w_kernel(const float* __restrict__ W) {
    int i = blockIdx.x * blockDim.x + threadIdx.x;
    if (i < VOCAB) {
        g_Wt[i] = make_float2(W[i], W[VOCAB + i]);
    }
}

// One block per batch row. 128 threads, each handles 4 tokens via int4 load.
__global__ __launch_bounds__(128) void bow_gather_kernel(
    const int* __restrict__ ids,
    const float* __restrict__ bias,
    float* __restrict__ out)
{
    const int row = blockIdx.x;
    const int4* rid = reinterpret_cast<const int4*>(ids + row * SEQ);

    const int t = threadIdx.x;  // 0..127, each covers 4 consecutive ids
    int4 v = rid[t];

    float s0 = 0.f, s1 = 0.f;
    // 4 independent gathers -> good MLP into L2.
    if (v.x != 0) { float2 w = g_Wt[v.x]; s0 += w.x; s1 += w.y; }
    if (v.y != 0) { float2 w = g_Wt[v.y]; s0 += w.x; s1 += w.y; }
    if (v.z != 0) { float2 w = g_Wt[v.z]; s0 += w.x; s1 += w.y; }
    if (v.w != 0) { float2 w = g_Wt[v.w]; s0 += w.x; s1 += w.y; }

    // Warp reduce
    #pragma unroll
    for (int o = 16; o > 0; o >>= 1) {
        s0 += __shfl_xor_sync(0xFFFFFFFFu, s0, o);
        s1 += __shfl_xor_sync(0xFFFFFFFFu, s1, o);
    }

    __shared__ float sm0[4], sm1[4];
    const int wid = t >> 5, lid = t & 31;
    if (lid == 0) { sm0[wid] = s0; sm1[wid] = s1; }
    __syncthreads();

    if (t == 0) {
        float r0 = sm0[0] + sm0[1] + sm0[2] + sm0[3];
        float r1 = sm1[0] + sm1[1] + sm1[2] + sm1[3];
        out[row * 2 + 0] = r0 + bias[0];
        out[row * 2 + 1] = r1 + bias[1];
    }
}

extern "C" void kernel_launch(void* const* d_in, const int* in_sizes, int n_in,
                              void* d_out, int out_size) {
    const int*   ids  = (const int*)d_in[0];    // [512, 512] int32
    const float* W    = (const float*)d_in[1];  // [2, 50257] float32
    const float* bias = (const float*)d_in[2];  // [2] float32
    float* out = (float*)d_out;                 // [512, 2] float32

    pack_w_kernel<<<(VOCAB + 255) / 256, 256>>>(W);
    bow_gather_kernel<<<BATCH, 128>>>(ids, bias, out);
}

// round 2
// speedup vs baseline: 1.0504x; 1.0504x over previous
#include <cuda_runtime.h>
#include <cuda_bf16.h>
#include <cstdint>

#define VOCAB 50257
#define BATCH 512
#define SEQ   512

// One CTA per batch row, one thread per token. No pre-pack: gather both
// class weights directly (both rows L2-resident, ~402 KB total).
__global__ __launch_bounds__(SEQ) void bow_fused_kernel(
    const int* __restrict__ ids,
    const float* __restrict__ W,     // [2, VOCAB] row-major
    const float* __restrict__ bias,  // [2]
    float* __restrict__ out)         // [BATCH, 2]
{
    const int row = blockIdx.x;
    const int t   = threadIdx.x;

    const int id = __ldg(ids + row * SEQ + t);

    float s0 = 0.f, s1 = 0.f;
    if (id != 0) {
        s0 = __ldg(W + id);
        s1 = __ldg(W + VOCAB + id);
    }

    // Warp reduce
    #pragma unroll
    for (int o = 16; o > 0; o >>= 1) {
        s0 += __shfl_xor_sync(0xFFFFFFFFu, s0, o);
        s1 += __shfl_xor_sync(0xFFFFFFFFu, s1, o);
    }

    __shared__ float sm0[16], sm1[16];
    const int wid = t >> 5, lid = t & 31;
    if (lid == 0) { sm0[wid] = s0; sm1[wid] = s1; }
    __syncthreads();

    // First warp reduces the 16 per-warp partials.
    if (wid == 0) {
        float r0 = (lid < 16) ? sm0[lid] : 0.f;
        float r1 = (lid < 16) ? sm1[lid] : 0.f;
        #pragma unroll
        for (int o = 8; o > 0; o >>= 1) {
            r0 += __shfl_xor_sync(0xFFFFFFFFu, r0, o);
            r1 += __shfl_xor_sync(0xFFFFFFFFu, r1, o);
        }
        if (lid == 0) {
            out[row * 2 + 0] = r0 + __ldg(bias + 0);
            out[row * 2 + 1] = r1 + __ldg(bias + 1);
        }
    }
}

extern "C" void kernel_launch(void* const* d_in, const int* in_sizes, int n_in,
                              void* d_out, int out_size) {
    const int*   ids  = (const int*)d_in[0];    // [512, 512] int32
    const float* W    = (const float*)d_in[1];  // [2, 50257] float32
    const float* bias = (const float*)d_in[2];  // [2] float32
    float* out = (float*)d_out;                 // [512, 2] float32

    bow_fused_kernel<<<BATCH, SEQ>>>(ids, W, bias, out);
}